// round 7
// baseline (speedup 1.0000x reference)
#include <cuda_runtime.h>
#include <cuda_bf16.h>
#include <cstdint>

#define NT 49
#define CD 128

/* float-index smem offsets */
#define FB      8192      /* QKV B slab (48KB) / proj B (64KB) at byte 32768 */
#define FS      9216      /* S f32 [2][49][52] (attention phase only) */
#define FQb     24576     /* Q split-bf16 [4][2][64][40] */
#define FKb     34816     /* K split-bf16 [4][2][64][40] */
#define FVt     45056     /* V^T split-bf16 [4][2][32][72] */
#define F_BT    54272     /* bias table 676 f32 */
#define F_RPI   54948     /* rpi u8 [2401] (601 fl) */
#define F_QB    55549     /* qkv_b 384 */
#define F_PB    55933     /* proj_b 128 */
#define F_BOUNCE 24576    /* out bounce [49][132] (Q region dead) */
#define BO_LD   132
#define SMEM_BYTES (56064*4)

__device__ __align__(16) uint16_t g_qkvw[98304];  /* [slab2][split2][384][64] swizzled bf16 */
__device__ __align__(16) uint16_t g_projw[32768]; /* [split2][128][128] swizzled bf16 */

__device__ __forceinline__ uint32_t smem_u32(const void* p) {
    uint32_t a;
    asm("{ .reg .u64 t; cvta.to.shared.u64 t, %1; cvt.u32.u64 %0, t; }" : "=r"(a) : "l"(p));
    return a;
}
__device__ __forceinline__ void ldsm4(uint32_t* r, uint32_t a) {
    asm volatile("ldmatrix.sync.aligned.m8n8.x4.shared.b16 {%0,%1,%2,%3}, [%4];"
        : "=r"(r[0]), "=r"(r[1]), "=r"(r[2]), "=r"(r[3]) : "r"(a));
}
__device__ __forceinline__ void mma_bf16(float* d, const uint32_t* a, const uint32_t* b) {
    asm volatile("mma.sync.aligned.m16n8k16.row.col.f32.bf16.bf16.f32 "
        "{%0,%1,%2,%3}, {%4,%5,%6,%7}, {%8,%9}, {%0,%1,%2,%3};"
        : "+f"(d[0]), "+f"(d[1]), "+f"(d[2]), "+f"(d[3])
        : "r"(a[0]), "r"(a[1]), "r"(a[2]), "r"(a[3]), "r"(b[0]), "r"(b[1]));
}
__device__ __forceinline__ float warp_max(float v) {
#pragma unroll
    for (int o = 16; o > 0; o >>= 1) v = fmaxf(v, __shfl_xor_sync(0xffffffffu, v, o));
    return v;
}
__device__ __forceinline__ float warp_sum(float v) {
#pragma unroll
    for (int o = 16; o > 0; o >>= 1) v += __shfl_xor_sync(0xffffffffu, v, o);
    return v;
}
__device__ __forceinline__ uint32_t pack_hi(float a, float b) {
    __nv_bfloat16 h0 = __float2bfloat16_rn(a), h1 = __float2bfloat16_rn(b);
    return (uint32_t)__bfloat16_as_ushort(h0) | ((uint32_t)__bfloat16_as_ushort(h1) << 16);
}
__device__ __forceinline__ uint32_t pack_lo(float a, float b) {
    __nv_bfloat16 h0 = __float2bfloat16_rn(a), h1 = __float2bfloat16_rn(b);
    float l0 = a - __bfloat162float(h0), l1 = b - __bfloat162float(h1);
    return (uint32_t)__bfloat16_as_ushort(__float2bfloat16_rn(l0)) |
           ((uint32_t)__bfloat16_as_ushort(__float2bfloat16_rn(l1)) << 16);
}

/* ---- prologue: split weights into bf16 hi/lo swizzled smem-images ---- */
__global__ void prep_w(const float* __restrict__ qkv_w, const float* __restrict__ proj_w) {
    int i = blockIdx.x * blockDim.x + threadIdx.x;
    if (i < 384 * 128) {
        int n = i >> 7, k = i & 127;
        float f = qkv_w[i];
        __nv_bfloat16 h = __float2bfloat16_rn(f);
        __nv_bfloat16 l = __float2bfloat16_rn(f - __bfloat162float(h));
        int s = k >> 6, ko = k & 63;
        int sw = (((ko >> 3) ^ (n & 7)) << 3) + (k & 7);
        g_qkvw[((s * 2 + 0) * 384 + n) * 64 + sw] = __bfloat16_as_ushort(h);
        g_qkvw[((s * 2 + 1) * 384 + n) * 64 + sw] = __bfloat16_as_ushort(l);
    }
    if (i < 128 * 128) {
        int n = i >> 7, k = i & 127;
        float f = proj_w[i];
        __nv_bfloat16 h = __float2bfloat16_rn(f);
        __nv_bfloat16 l = __float2bfloat16_rn(f - __bfloat162float(h));
        int sw = (((k >> 3) ^ (n & 7)) << 3) + (k & 7);
        g_projw[(0 * 128 + n) * 128 + sw] = __bfloat16_as_ushort(h);
        g_projw[(1 * 128 + n) * 128 + sw] = __bfloat16_as_ushort(l);
    }
}

/* ---- main fused kernel ---- */
__global__ __launch_bounds__(512, 1)
void win_attn_mma(const float* __restrict__ x,
                  const float* __restrict__ mask,
                  const float* __restrict__ qkv_b,
                  const float* __restrict__ proj_b,
                  const float* __restrict__ bt,
                  float* __restrict__ out,
                  int nW)
{
    extern __shared__ float sm[];
    uint16_t* u16b = (uint16_t*)sm;      /* bf16 overlay: QKV-A / P at 0; Qb/Kb/Vt via indices */
    const int t = threadIdx.x;
    const int w = blockIdx.x;
    const long base = (long)w * (NT * CD);
    const int tn = t & 31, tm = t >> 5;
    const uint32_t smb = smem_u32(sm);

    /* ---- stage x -> A hi/lo (swizzled bf16); pads; tables; biases ---- */
    for (int idx = t; idx < NT * CD; idx += 512) {
        int r = idx >> 7, k = idx & 127;
        float f = x[base + idx];
        __nv_bfloat16 h = __float2bfloat16_rn(f);
        __nv_bfloat16 l = __float2bfloat16_rn(f - __bfloat162float(h));
        int sw = ((k >> 3) ^ (r & 7)) * 8 + (k & 7);
        u16b[r * 128 + sw]        = __bfloat16_as_ushort(h);
        u16b[(64 + r) * 128 + sw] = __bfloat16_as_ushort(l);
    }
    for (int idx = t; idx < 15 * CD; idx += 512) {
        int r = 49 + (idx >> 7), k = idx & 127;
        int sw = ((k >> 3) ^ (r & 7)) * 8 + (k & 7);
        u16b[r * 128 + sw] = 0;
        u16b[(64 + r) * 128 + sw] = 0;
    }
    if (t < 384) sm[F_QB + t] = qkv_b[t];
    if (t < 128) sm[F_PB + t] = proj_b[t];
    for (int idx = t; idx < 676; idx += 512) sm[F_BT + idx] = bt[idx];
    {   /* rpi table u8[49][49] */
        uint8_t* rp = (uint8_t*)(sm + F_RPI);
        for (int idx = t; idx < NT * NT; idx += 512) {
            int i = idx / NT, j = idx - i * NT;
            int yi = i / 7, xi = i - yi * 7;
            int yj = j / 7, xj = j - yj * 7;
            rp[idx] = (uint8_t)((yi - yj + 6) * 13 + (xi - xj + 6));
        }
    }
    __syncthreads();

    const int l = tn;
    const int wm = tm & 1, wn = tm >> 1;
    const int a_r_off = (l & 7) + ((l >> 3) & 1) * 8;   /* == l&15 */
    const int a_c_off = l >> 4;
    const int b_n_off = (l & 7) + (l >> 4) * 8;
    const int b_c_off = (l >> 3) & 1;

    /* ======== QKV GEMM: D[64x384] = A[64x128] @ W^T, split-bf16 ======== */
    float dacc[2][6][4];
#pragma unroll
    for (int a = 0; a < 2; a++)
#pragma unroll
        for (int b = 0; b < 6; b++)
#pragma unroll
            for (int c = 0; c < 4; c++) dacc[a][b][c] = 0.f;

    for (int s = 0; s < 2; s++)
        for (int bsp = 0; bsp < 2; bsp++) {
            {   /* stage one split of B k-slab: [384][64] bf16 = 3072 float4 */
                const float4* src = ((const float4*)g_qkvw) + (s * 2 + bsp) * 3072;
                float4* dst = (float4*)(sm + FB);
                for (int i = t; i < 3072; i += 512) dst[i] = src[i];
            }
            __syncthreads();
#pragma unroll
            for (int kk = 0; kk < 4; kk++) {
                uint32_t afh[2][4], afl[2][4];
#pragma unroll
                for (int mt = 0; mt < 2; mt++) {
                    int r = wm * 32 + mt * 16 + a_r_off;
                    int ch = s * 8 + kk * 2 + a_c_off;
                    uint32_t ad = smb + (((r * 128) + ((ch ^ (r & 7)) << 3)) << 1);
                    ldsm4(afh[mt], ad);
                    if (bsp == 0) ldsm4(afl[mt], ad + (64 * 128 * 2));
                }
                uint32_t bf[6][2];
#pragma unroll
                for (int np = 0; np < 3; np++) {
                    int n = wn * 48 + np * 16 + b_n_off;
                    int ch = kk * 2 + b_c_off;
                    uint32_t ad = smb + FB * 4 + (((n * 64) + ((ch ^ (n & 7)) << 3)) << 1);
                    uint32_t r4[4]; ldsm4(r4, ad);
                    bf[np * 2][0] = r4[0]; bf[np * 2][1] = r4[1];
                    bf[np * 2 + 1][0] = r4[2]; bf[np * 2 + 1][1] = r4[3];
                }
#pragma unroll
                for (int mt = 0; mt < 2; mt++)
#pragma unroll
                    for (int nt = 0; nt < 6; nt++) {
                        mma_bf16(dacc[mt][nt], afh[mt], bf[nt]);
                        if (bsp == 0) mma_bf16(dacc[mt][nt], afl[mt], bf[nt]);
                    }
            }
            __syncthreads();
        }

    /* ---- QKV epilogue: fragments -> Qb (x scale) / Kb / Vt, split-bf16 ---- */
    {
        const float scale = 0.1767766952966369f;
        int r0 = wm * 32 + (l >> 2);
#pragma unroll
        for (int mt = 0; mt < 2; mt++)
#pragma unroll
            for (int nt = 0; nt < 6; nt++)
#pragma unroll
                for (int rh = 0; rh < 2; rh++) {
                    int row = r0 + mt * 16 + rh * 8;
                    if (row >= NT) continue;
                    int c = wn * 48 + nt * 8 + (l & 3) * 2;
                    float v0 = dacc[mt][nt][rh * 2]     + sm[F_QB + c];
                    float v1 = dacc[mt][nt][rh * 2 + 1] + sm[F_QB + c + 1];
                    if (c < 128) {
                        v0 *= scale; v1 *= scale;
                        int h = c >> 5, dh = c & 31;
                        int i0 = ((h * 2 + 0) * 64 + row) * 40 + dh;
                        int i1 = ((h * 2 + 1) * 64 + row) * 40 + dh;
                        *(uint32_t*)&u16b[FQb * 2 + i0] = pack_hi(v0, v1);
                        *(uint32_t*)&u16b[FQb * 2 + i1] = pack_lo(v0, v1);
                    } else if (c < 256) {
                        int h = (c - 128) >> 5, dh = (c - 128) & 31;
                        int i0 = ((h * 2 + 0) * 64 + row) * 40 + dh;
                        int i1 = ((h * 2 + 1) * 64 + row) * 40 + dh;
                        *(uint32_t*)&u16b[FKb * 2 + i0] = pack_hi(v0, v1);
                        *(uint32_t*)&u16b[FKb * 2 + i1] = pack_lo(v0, v1);
                    } else {
                        int h = (c - 256) >> 5, dh = (c - 256) & 31;
                        __nv_bfloat16 h0 = __float2bfloat16_rn(v0);
                        __nv_bfloat16 h1 = __float2bfloat16_rn(v1);
                        __nv_bfloat16 l0 = __float2bfloat16_rn(v0 - __bfloat162float(h0));
                        __nv_bfloat16 l1 = __float2bfloat16_rn(v1 - __bfloat162float(h1));
                        int bh = FVt * 2 + ((h * 2 + 0) * 32 + dh) * 72 + row;
                        int bl = FVt * 2 + ((h * 2 + 1) * 32 + dh) * 72 + row;
                        u16b[bh]      = __bfloat16_as_ushort(h0);
                        u16b[bh + 72] = __bfloat16_as_ushort(h1);
                        u16b[bl]      = __bfloat16_as_ushort(l0);
                        u16b[bl + 72] = __bfloat16_as_ushort(l1);
                    }
                }
    }
    /* zero Vt key-pad cols 49..63 (NaN safety vs zero P pads) */
    for (int i = t; i < 8 * 32 * 15; i += 512) {
        int hs = i / (32 * 15), rem = i - hs * (32 * 15);
        int dh = rem / 15, jj = rem - dh * 15;
        u16b[FVt * 2 + (hs * 32 + dh) * 72 + 49 + jj] = 0;
    }
    __syncthreads();

    /* ======== attention via mma, 2 heads per pass ======== */
    const float* mrow = mask + (long)(w % nW) * (NT * NT);
    const uint8_t* rp = (const uint8_t*)(sm + F_RPI);
    const int hh = tm >> 3, mt = tm & 3, nh = (tm >> 2) & 1;

    float oacc[2][2][4];
#pragma unroll
    for (int a = 0; a < 2; a++)
#pragma unroll
        for (int b = 0; b < 2; b++)
#pragma unroll
            for (int c = 0; c < 4; c++) oacc[a][b][c] = 0.f;

#pragma unroll
    for (int pr = 0; pr < 2; pr++) {
        const int h = pr * 2 + hh;
        /* ---- S = (Q*scale) K^T ---- */
        float sacc[4][4];
#pragma unroll
        for (int a = 0; a < 4; a++)
#pragma unroll
            for (int c = 0; c < 4; c++) sacc[a][c] = 0.f;
#pragma unroll
        for (int kk = 0; kk < 2; kk++) {
            uint32_t aq[2][4];
#pragma unroll
            for (int sp = 0; sp < 2; sp++) {
                int r = mt * 16 + a_r_off;
                uint32_t ad = smb + FQb * 4 +
                    ((((h * 2 + sp) * 64 + r) * 40 + (kk * 2 + a_c_off) * 8) << 1);
                ldsm4(aq[sp], ad);
            }
            uint32_t bk[4][2][2];
#pragma unroll
            for (int p2 = 0; p2 < 2; p2++)
#pragma unroll
                for (int sp = 0; sp < 2; sp++) {
                    int n = nh * 32 + p2 * 16 + b_n_off;
                    uint32_t ad = smb + FKb * 4 +
                        ((((h * 2 + sp) * 64 + n) * 40 + (kk * 2 + b_c_off) * 8) << 1);
                    uint32_t r4[4]; ldsm4(r4, ad);
                    bk[p2 * 2][sp][0] = r4[0]; bk[p2 * 2][sp][1] = r4[1];
                    bk[p2 * 2 + 1][sp][0] = r4[2]; bk[p2 * 2 + 1][sp][1] = r4[3];
                }
#pragma unroll
            for (int nt = 0; nt < 4; nt++) {
                mma_bf16(sacc[nt], aq[0], bk[nt][0]);
                mma_bf16(sacc[nt], aq[0], bk[nt][1]);
                mma_bf16(sacc[nt], aq[1], bk[nt][0]);
            }
        }
        /* S fragments -> smem f32 */
#pragma unroll
        for (int nt = 0; nt < 4; nt++)
#pragma unroll
            for (int rh = 0; rh < 2; rh++) {
                int row = mt * 16 + (l >> 2) + rh * 8;
                int c = nh * 32 + nt * 8 + (l & 3) * 2;
                if (row < NT && c < NT) {
                    int idx = FS + (hh * NT + row) * 52 + c;
                    if (c + 1 < NT)
                        *(float2*)&sm[idx] = make_float2(sacc[nt][rh * 2], sacc[nt][rh * 2 + 1]);
                    else
                        sm[idx] = sacc[nt][rh * 2];
                }
            }
        __syncthreads();

        /* ---- softmax (+bias+mask) -> P split-bf16 (aliases QKV A/B region) ---- */
        for (int p = 0; p < 7; p++) {
            int r = (tm & 7) + 8 * p;
            if (r < NT) {
                int c0 = 2 * l, c1 = 2 * l + 1;
                float v0 = -1e30f, v1 = -1e30f;
                if (c0 < NT) {
                    float2 sv = *(const float2*)&sm[FS + (hh * NT + r) * 52 + c0];
                    v0 = sv.x + sm[F_BT + rp[r * NT + c0] * 4 + h] + mrow[r * NT + c0];
                    if (c1 < NT)
                        v1 = sv.y + sm[F_BT + rp[r * NT + c1] * 4 + h] + mrow[r * NT + c1];
                }
                float m = warp_max(fmaxf(v0, v1));
                float e0 = (c0 < NT) ? __expf(v0 - m) : 0.f;
                float e1 = (c1 < NT) ? __expf(v1 - m) : 0.f;
                float inv = 1.f / warp_sum(e0 + e1);
                float p0 = e0 * inv, p1 = e1 * inv;
                int i0 = ((hh * 2 + 0) * 64 + r) * 72 + c0;
                int i1 = ((hh * 2 + 1) * 64 + r) * 72 + c0;
                *(uint32_t*)&u16b[i0] = pack_hi(p0, p1);
                *(uint32_t*)&u16b[i1] = pack_lo(p0, p1);
            }
        }
        __syncthreads();

        /* ---- O_h = P V ---- */
#pragma unroll
        for (int kk = 0; kk < 4; kk++) {
            uint32_t ap[2][4];
#pragma unroll
            for (int sp = 0; sp < 2; sp++) {
                int r = mt * 16 + a_r_off;
                uint32_t ad = smb +
                    ((((hh * 2 + sp) * 64 + r) * 72 + (kk * 2 + a_c_off) * 8) << 1);
                ldsm4(ap[sp], ad);
            }
            uint32_t bv[2][2][2];
#pragma unroll
            for (int sp = 0; sp < 2; sp++) {
                int n = nh * 16 + b_n_off;
                uint32_t ad = smb + FVt * 4 +
                    ((((h * 2 + sp) * 32 + n) * 72 + (kk * 2 + b_c_off) * 8) << 1);
                uint32_t r4[4]; ldsm4(r4, ad);
                bv[0][sp][0] = r4[0]; bv[0][sp][1] = r4[1];
                bv[1][sp][0] = r4[2]; bv[1][sp][1] = r4[3];
            }
#pragma unroll
            for (int nt = 0; nt < 2; nt++) {
                mma_bf16(oacc[pr][nt], ap[0], bv[nt][0]);
                mma_bf16(oacc[pr][nt], ap[0], bv[nt][1]);
                mma_bf16(oacc[pr][nt], ap[1], bv[nt][0]);
            }
        }
        __syncthreads();   /* PV done before next pass overwrites S/P */
    }

    /* ---- O fragments -> proj-A split-bf16 swizzled (region at 0; P dead) ---- */
#pragma unroll
    for (int pr = 0; pr < 2; pr++)
#pragma unroll
        for (int nt = 0; nt < 2; nt++)
#pragma unroll
            for (int rh = 0; rh < 2; rh++) {
                int row = mt * 16 + (l >> 2) + rh * 8;
                int h = pr * 2 + hh;
                int c = h * 32 + nh * 16 + nt * 8 + (l & 3) * 2;
                float v0 = oacc[pr][nt][rh * 2], v1 = oacc[pr][nt][rh * 2 + 1];
                int sw = (((c >> 3) ^ (row & 7)) << 3) + (c & 7);
                *(uint32_t*)&u16b[row * 128 + sw]        = pack_hi(v0, v1);
                *(uint32_t*)&u16b[(64 + row) * 128 + sw] = pack_lo(v0, v1);
            }
    __syncthreads();

    /* ======== proj GEMM: D[64x128] = O @ proj_w^T, split-bf16 ======== */
    {
        const float4* src = (const float4*)g_projw;
        float4* dst = (float4*)(sm + FB);
        for (int i = t; i < 4096; i += 512) dst[i] = src[i];
    }
    __syncthreads();

    float pacc[2][2][4];
#pragma unroll
    for (int a = 0; a < 2; a++)
#pragma unroll
        for (int b = 0; b < 2; b++)
#pragma unroll
            for (int c = 0; c < 4; c++) pacc[a][b][c] = 0.f;

#pragma unroll
    for (int kk = 0; kk < 8; kk++) {
        uint32_t af[2][2][4];
#pragma unroll
        for (int mt2 = 0; mt2 < 2; mt2++)
#pragma unroll
            for (int sp = 0; sp < 2; sp++) {
                int r = wm * 32 + mt2 * 16 + a_r_off;
                int ch = kk * 2 + a_c_off;
                uint32_t ad = smb + ((((sp * 64 + r) * 128) + ((ch ^ (r & 7)) << 3)) << 1);
                ldsm4(af[mt2][sp], ad);
            }
        uint32_t bf2[2][2][2];
#pragma unroll
        for (int sp = 0; sp < 2; sp++) {
            int n = wn * 16 + b_n_off;
            int ch = kk * 2 + b_c_off;
            uint32_t ad = smb + FB * 4 + ((((sp * 128 + n) * 128) + ((ch ^ (n & 7)) << 3)) << 1);
            uint32_t r4[4]; ldsm4(r4, ad);
            bf2[0][sp][0] = r4[0]; bf2[0][sp][1] = r4[1];
            bf2[1][sp][0] = r4[2]; bf2[1][sp][1] = r4[3];
        }
#pragma unroll
        for (int mt2 = 0; mt2 < 2; mt2++)
#pragma unroll
            for (int nt = 0; nt < 2; nt++) {
                mma_bf16(pacc[mt2][nt], af[mt2][0], bf2[nt][0]);
                mma_bf16(pacc[mt2][nt], af[mt2][0], bf2[nt][1]);
                mma_bf16(pacc[mt2][nt], af[mt2][1], bf2[nt][0]);
            }
    }
    __syncthreads();

    /* ---- proj epilogue: accum+bias -> bounce -> coalesced store ---- */
    {
        int r0 = wm * 32 + (l >> 2);
#pragma unroll
        for (int mt2 = 0; mt2 < 2; mt2++)
#pragma unroll
            for (int nt = 0; nt < 2; nt++)
#pragma unroll
                for (int rg = 0; rg < 4; rg++) {
                    int row = r0 + mt2 * 16 + ((rg >> 1) << 3);
                    int col = wn * 16 + nt * 8 + (l & 3) * 2 + (rg & 1);
                    if (row < NT)
                        sm[F_BOUNCE + row * BO_LD + col] = pacc[mt2][nt][rg] + sm[F_PB + col];
                }
    }
    __syncthreads();
    for (int idx = t; idx < NT * CD; idx += 512)
        out[base + idx] = sm[F_BOUNCE + (idx >> 7) * BO_LD + (idx & 127)];
}

extern "C" void kernel_launch(void* const* d_in, const int* in_sizes, int n_in,
                              void* d_out, int out_size) {
    const float* x      = (const float*)d_in[0];
    const float* mask   = (const float*)d_in[1];
    const float* qkv_w  = (const float*)d_in[2];
    const float* qkv_b  = (const float*)d_in[3];
    const float* proj_w = (const float*)d_in[4];
    const float* proj_b = (const float*)d_in[5];
    const float* bt     = (const float*)d_in[6];
    float* out = (float*)d_out;

    int B  = in_sizes[0] / (NT * CD);     /* 16384 */
    int nW = in_sizes[1] / (NT * NT);     /* 1024 */

    prep_w<<<96, 512>>>(qkv_w, proj_w);

    cudaFuncSetAttribute(win_attn_mma,
                         cudaFuncAttributeMaxDynamicSharedMemorySize, SMEM_BYTES);
    win_attn_mma<<<B, 512, SMEM_BYTES>>>(x, mask, qkv_b, proj_b, bt, out, nW);
}

// round 8
// speedup vs baseline: 1.1472x; 1.1472x over previous
#include <cuda_runtime.h>
#include <cuda_bf16.h>
#include <cstdint>

#define NT 49
#define CD 128

/* float-index smem offsets */
#define FB      8192      /* QKV B slab (48KB) / proj B both splits (64KB) */
#define FQb     24576     /* Q split-bf16 [4][2][64][40] */
#define FKb     34816     /* K split-bf16 [4][2][64][40] */
#define FVt     45056     /* V^T split-bf16 [4][2][32][72] */
#define F_BT    54272     /* bias table 676 f32 */
#define F_RPI   54948     /* rpi u8 [2401] */
#define F_QB    55549     /* qkv_b 384 */
#define F_PB    55933     /* proj_b 128 */
#define F_BOUNCE 24576    /* out bounce [49][132] (Qb dead) */
#define BO_LD   132
#define SMEM_BYTES (56064*4)

__device__ __align__(16) uint16_t g_qkvw[98304];  /* [slab2][split2][384][64] swizzled bf16 */
__device__ __align__(16) uint16_t g_projw[32768]; /* [split2][128][128] swizzled bf16 */

__device__ __forceinline__ uint32_t smem_u32(const void* p) {
    uint32_t a;
    asm("{ .reg .u64 t; cvta.to.shared.u64 t, %1; cvt.u32.u64 %0, t; }" : "=r"(a) : "l"(p));
    return a;
}
__device__ __forceinline__ void ldsm4(uint32_t* r, uint32_t a) {
    asm volatile("ldmatrix.sync.aligned.m8n8.x4.shared.b16 {%0,%1,%2,%3}, [%4];"
        : "=r"(r[0]), "=r"(r[1]), "=r"(r[2]), "=r"(r[3]) : "r"(a));
}
__device__ __forceinline__ void mma_bf16(float* d, const uint32_t* a, const uint32_t* b) {
    asm volatile("mma.sync.aligned.m16n8k16.row.col.f32.bf16.bf16.f32 "
        "{%0,%1,%2,%3}, {%4,%5,%6,%7}, {%8,%9}, {%0,%1,%2,%3};"
        : "+f"(d[0]), "+f"(d[1]), "+f"(d[2]), "+f"(d[3])
        : "r"(a[0]), "r"(a[1]), "r"(a[2]), "r"(a[3]), "r"(b[0]), "r"(b[1]));
}
__device__ __forceinline__ uint32_t pack_hi(float a, float b) {
    __nv_bfloat16 h0 = __float2bfloat16_rn(a), h1 = __float2bfloat16_rn(b);
    return (uint32_t)__bfloat16_as_ushort(h0) | ((uint32_t)__bfloat16_as_ushort(h1) << 16);
}
__device__ __forceinline__ uint32_t pack_lo(float a, float b) {
    __nv_bfloat16 h0 = __float2bfloat16_rn(a), h1 = __float2bfloat16_rn(b);
    float l0 = a - __bfloat162float(h0), l1 = b - __bfloat162float(h1);
    return (uint32_t)__bfloat16_as_ushort(__float2bfloat16_rn(l0)) |
           ((uint32_t)__bfloat16_as_ushort(__float2bfloat16_rn(l1)) << 16);
}

/* ---- prologue: split weights into bf16 hi/lo swizzled smem-images ---- */
__global__ void prep_w(const float* __restrict__ qkv_w, const float* __restrict__ proj_w) {
    int i = blockIdx.x * blockDim.x + threadIdx.x;
    if (i < 384 * 128) {
        int n = i >> 7, k = i & 127;
        float f = qkv_w[i];
        __nv_bfloat16 h = __float2bfloat16_rn(f);
        __nv_bfloat16 l = __float2bfloat16_rn(f - __bfloat162float(h));
        int s = k >> 6, ko = k & 63;
        int sw = (((ko >> 3) ^ (n & 7)) << 3) + (k & 7);
        g_qkvw[((s * 2 + 0) * 384 + n) * 64 + sw] = __bfloat16_as_ushort(h);
        g_qkvw[((s * 2 + 1) * 384 + n) * 64 + sw] = __bfloat16_as_ushort(l);
    }
    if (i < 128 * 128) {
        int n = i >> 7, k = i & 127;
        float f = proj_w[i];
        __nv_bfloat16 h = __float2bfloat16_rn(f);
        __nv_bfloat16 l = __float2bfloat16_rn(f - __bfloat162float(h));
        int sw = (((k >> 3) ^ (n & 7)) << 3) + (k & 7);
        g_projw[(0 * 128 + n) * 128 + sw] = __bfloat16_as_ushort(h);
        g_projw[(1 * 128 + n) * 128 + sw] = __bfloat16_as_ushort(l);
    }
}

/* ---- main fused kernel ---- */
__global__ __launch_bounds__(512, 1)
void win_attn_mma(const float* __restrict__ x,
                  const float* __restrict__ mask,
                  const float* __restrict__ qkv_b,
                  const float* __restrict__ proj_b,
                  const float* __restrict__ bt,
                  float* __restrict__ out,
                  int nW)
{
    extern __shared__ float sm[];
    uint16_t* u16b = (uint16_t*)sm;
    const int t = threadIdx.x;
    const int w = blockIdx.x;
    const long base = (long)w * (NT * CD);
    const int tn = t & 31, tm = t >> 5;
    const uint32_t smb = smem_u32(sm);

    /* ---- stage x -> A hi/lo (swizzled bf16); pads; tables; biases ---- */
    for (int idx = t; idx < NT * CD; idx += 512) {
        int r = idx >> 7, k = idx & 127;
        float f = x[base + idx];
        __nv_bfloat16 h = __float2bfloat16_rn(f);
        __nv_bfloat16 l = __float2bfloat16_rn(f - __bfloat162float(h));
        int sw = ((k >> 3) ^ (r & 7)) * 8 + (k & 7);
        u16b[r * 128 + sw]        = __bfloat16_as_ushort(h);
        u16b[(64 + r) * 128 + sw] = __bfloat16_as_ushort(l);
    }
    for (int idx = t; idx < 15 * CD; idx += 512) {
        int r = 49 + (idx >> 7), k = idx & 127;
        int sw = ((k >> 3) ^ (r & 7)) * 8 + (k & 7);
        u16b[r * 128 + sw] = 0;
        u16b[(64 + r) * 128 + sw] = 0;
    }
    if (t < 384) sm[F_QB + t] = qkv_b[t];
    if (t < 128) sm[F_PB + t] = proj_b[t];
    for (int idx = t; idx < 676; idx += 512) sm[F_BT + idx] = bt[idx];
    {   /* rpi table u8[49][49] */
        uint8_t* rpw = (uint8_t*)(sm + F_RPI);
        for (int idx = t; idx < NT * NT; idx += 512) {
            int i = idx / NT, j = idx - i * NT;
            int yi = i / 7, xi = i - yi * 7;
            int yj = j / 7, xj = j - yj * 7;
            rpw[idx] = (uint8_t)((yi - yj + 6) * 13 + (xi - xj + 6));
        }
    }
    __syncthreads();

    const int l = tn;
    const int wm = tm & 1, wn = tm >> 1;
    const int a_r_off = l & 15;
    const int a_c_off = l >> 4;
    const int b_n_off = (l & 7) + (l >> 4) * 8;
    const int b_c_off = (l >> 3) & 1;

    /* ======== QKV GEMM: D[64x384] = A[64x128] @ W^T, split-bf16 ======== */
    float dacc[2][6][4];
#pragma unroll
    for (int a = 0; a < 2; a++)
#pragma unroll
        for (int b = 0; b < 6; b++)
#pragma unroll
            for (int c = 0; c < 4; c++) dacc[a][b][c] = 0.f;

    for (int s = 0; s < 2; s++)
        for (int bsp = 0; bsp < 2; bsp++) {
            {   /* stage one split of B k-slab: [384][64] bf16 = 3072 float4 */
                const float4* src = ((const float4*)g_qkvw) + (s * 2 + bsp) * 3072;
                float4* dst = (float4*)(sm + FB);
                for (int i = t; i < 3072; i += 512) dst[i] = src[i];
            }
            __syncthreads();
#pragma unroll
            for (int kk = 0; kk < 4; kk++) {
                uint32_t afh[2][4], afl[2][4];
#pragma unroll
                for (int mt = 0; mt < 2; mt++) {
                    int r = wm * 32 + mt * 16 + a_r_off;
                    int ch = s * 8 + kk * 2 + a_c_off;
                    uint32_t ad = smb + (((r * 128) + ((ch ^ (r & 7)) << 3)) << 1);
                    ldsm4(afh[mt], ad);
                    if (bsp == 0) ldsm4(afl[mt], ad + (64 * 128 * 2));
                }
                uint32_t bf[6][2];
#pragma unroll
                for (int np = 0; np < 3; np++) {
                    int n = wn * 48 + np * 16 + b_n_off;
                    int ch = kk * 2 + b_c_off;
                    uint32_t ad = smb + FB * 4 + (((n * 64) + ((ch ^ (n & 7)) << 3)) << 1);
                    uint32_t r4[4]; ldsm4(r4, ad);
                    bf[np * 2][0] = r4[0]; bf[np * 2][1] = r4[1];
                    bf[np * 2 + 1][0] = r4[2]; bf[np * 2 + 1][1] = r4[3];
                }
#pragma unroll
                for (int mt = 0; mt < 2; mt++)
#pragma unroll
                    for (int nt = 0; nt < 6; nt++) {
                        mma_bf16(dacc[mt][nt], afh[mt], bf[nt]);
                        if (bsp == 0) mma_bf16(dacc[mt][nt], afl[mt], bf[nt]);
                    }
            }
            __syncthreads();
        }

    /* ---- QKV epilogue: fragments -> Qb (x scale) / Kb / Vt, split-bf16 ---- */
    {
        const float scale = 0.1767766952966369f;
        int r0 = wm * 32 + (l >> 2);
#pragma unroll
        for (int mt = 0; mt < 2; mt++)
#pragma unroll
            for (int nt = 0; nt < 6; nt++)
#pragma unroll
                for (int rh = 0; rh < 2; rh++) {
                    int row = r0 + mt * 16 + rh * 8;
                    if (row >= NT) continue;
                    int c = wn * 48 + nt * 8 + (l & 3) * 2;
                    float v0 = dacc[mt][nt][rh * 2]     + sm[F_QB + c];
                    float v1 = dacc[mt][nt][rh * 2 + 1] + sm[F_QB + c + 1];
                    if (c < 128) {
                        v0 *= scale; v1 *= scale;
                        int h = c >> 5, dh = c & 31;
                        int i0 = ((h * 2 + 0) * 64 + row) * 40 + dh;
                        int i1 = ((h * 2 + 1) * 64 + row) * 40 + dh;
                        *(uint32_t*)&u16b[FQb * 2 + i0] = pack_hi(v0, v1);
                        *(uint32_t*)&u16b[FQb * 2 + i1] = pack_lo(v0, v1);
                    } else if (c < 256) {
                        int h = (c - 128) >> 5, dh = (c - 128) & 31;
                        int i0 = ((h * 2 + 0) * 64 + row) * 40 + dh;
                        int i1 = ((h * 2 + 1) * 64 + row) * 40 + dh;
                        *(uint32_t*)&u16b[FKb * 2 + i0] = pack_hi(v0, v1);
                        *(uint32_t*)&u16b[FKb * 2 + i1] = pack_lo(v0, v1);
                    } else {
                        int h = (c - 256) >> 5, dh = (c - 256) & 31;
                        __nv_bfloat16 h0 = __float2bfloat16_rn(v0);
                        __nv_bfloat16 h1 = __float2bfloat16_rn(v1);
                        __nv_bfloat16 l0 = __float2bfloat16_rn(v0 - __bfloat162float(h0));
                        __nv_bfloat16 l1 = __float2bfloat16_rn(v1 - __bfloat162float(h1));
                        int bh = FVt * 2 + ((h * 2 + 0) * 32 + dh) * 72 + row;
                        int bl = FVt * 2 + ((h * 2 + 1) * 32 + dh) * 72 + row;
                        u16b[bh]      = __bfloat16_as_ushort(h0);
                        u16b[bh + 72] = __bfloat16_as_ushort(h1);
                        u16b[bl]      = __bfloat16_as_ushort(l0);
                        u16b[bl + 72] = __bfloat16_as_ushort(l1);
                    }
                }
    }
    /* zero Vt key-pad cols 49..63 (0*garbage != NaN safety) */
    for (int i = t; i < 8 * 32 * 15; i += 512) {
        int hs = i / (32 * 15), rem = i - hs * (32 * 15);
        int dh = rem / 15, jj = rem - dh * 15;
        u16b[FVt * 2 + (hs * 32 + dh) * 72 + 49 + jj] = 0;
    }
    /* stage proj B now (both splits, 4096 float4) — latency hides behind attention */
    {
        const float4* src = (const float4*)g_projw;
        float4* dst = (float4*)(sm + FB);
        for (int i = t; i < 4096; i += 512) dst[i] = src[i];
    }
    __syncthreads();

    /* ======== attention, fully register-resident: 16 warps = 4 heads x 4 m-tiles ======== */
    const float* mrow = mask + (long)(w % nW) * (NT * NT);
    const uint8_t* rp = (const uint8_t*)(sm + F_RPI);
    const int h = tm >> 2, amt = tm & 3;
    const int cbase = (l & 3) * 2;
    const int r0 = amt * 16 + (l >> 2);
    const int r1 = r0 + 8;

    /* ---- S = (Q*scale) K^T : m16 x n64 per warp ---- */
    float sacc[8][4];
#pragma unroll
    for (int a = 0; a < 8; a++)
#pragma unroll
        for (int c = 0; c < 4; c++) sacc[a][c] = 0.f;

#pragma unroll
    for (int kk = 0; kk < 2; kk++) {
        uint32_t aq[2][4];
#pragma unroll
        for (int sp = 0; sp < 2; sp++)
            ldsm4(aq[sp], smb + FQb * 4 +
                ((((h * 2 + sp) * 64 + amt * 16 + a_r_off) * 40 + (kk * 2 + a_c_off) * 8) << 1));
        uint32_t bk[8][2][2];
#pragma unroll
        for (int g = 0; g < 4; g++)
#pragma unroll
            for (int sp = 0; sp < 2; sp++) {
                uint32_t r4[4];
                ldsm4(r4, smb + FKb * 4 +
                    ((((h * 2 + sp) * 64 + g * 16 + b_n_off) * 40 + (kk * 2 + b_c_off) * 8) << 1));
                bk[g * 2][sp][0] = r4[0]; bk[g * 2][sp][1] = r4[1];
                bk[g * 2 + 1][sp][0] = r4[2]; bk[g * 2 + 1][sp][1] = r4[3];
            }
#pragma unroll
        for (int nt = 0; nt < 8; nt++) {
            mma_bf16(sacc[nt], aq[0], bk[nt][0]);
            mma_bf16(sacc[nt], aq[0], bk[nt][1]);
            mma_bf16(sacc[nt], aq[1], bk[nt][0]);
        }
    }

    /* ---- softmax in registers (+bias+mask); rows reduce over 4 lanes ---- */
    {
        int r0c = (r0 < NT) ? r0 : (NT - 1);
        int r1c = (r1 < NT) ? r1 : (NT - 1);
        float m0 = -1e30f, m1 = -1e30f;
#pragma unroll
        for (int nt = 0; nt < 8; nt++)
#pragma unroll
            for (int j = 0; j < 2; j++) {
                int c = nt * 8 + cbase + j;
                if (c < NT) {
                    float bi0 = sm[F_BT + rp[r0c * NT + c] * 4 + h];
                    float bi1 = sm[F_BT + rp[r1c * NT + c] * 4 + h];
                    float mk0 = (r0 < NT) ? mrow[r0 * NT + c] : 0.f;
                    float mk1 = (r1 < NT) ? mrow[r1 * NT + c] : 0.f;
                    sacc[nt][j]     += bi0 + mk0;
                    sacc[nt][2 + j] += bi1 + mk1;
                } else {
                    sacc[nt][j] = -1e30f;
                    sacc[nt][2 + j] = -1e30f;
                }
                m0 = fmaxf(m0, sacc[nt][j]);
                m1 = fmaxf(m1, sacc[nt][2 + j]);
            }
        m0 = fmaxf(m0, __shfl_xor_sync(0xffffffffu, m0, 1));
        m0 = fmaxf(m0, __shfl_xor_sync(0xffffffffu, m0, 2));
        m1 = fmaxf(m1, __shfl_xor_sync(0xffffffffu, m1, 1));
        m1 = fmaxf(m1, __shfl_xor_sync(0xffffffffu, m1, 2));
        float s0 = 0.f, s1 = 0.f;
#pragma unroll
        for (int nt = 0; nt < 8; nt++)
#pragma unroll
            for (int j = 0; j < 2; j++) {
                float e0 = __expf(sacc[nt][j] - m0);
                float e1 = __expf(sacc[nt][2 + j] - m1);
                sacc[nt][j] = e0; sacc[nt][2 + j] = e1;
                s0 += e0; s1 += e1;
            }
        s0 += __shfl_xor_sync(0xffffffffu, s0, 1);
        s0 += __shfl_xor_sync(0xffffffffu, s0, 2);
        s1 += __shfl_xor_sync(0xffffffffu, s1, 1);
        s1 += __shfl_xor_sync(0xffffffffu, s1, 2);
        float i0 = 1.f / s0, i1 = 1.f / s1;
#pragma unroll
        for (int nt = 0; nt < 8; nt++)
#pragma unroll
            for (int j = 0; j < 2; j++) { sacc[nt][j] *= i0; sacc[nt][2 + j] *= i1; }
    }

    /* ---- O = P V : P fragments straight from registers (D-layout == A-layout) ---- */
    float oacc[4][4];
#pragma unroll
    for (int a = 0; a < 4; a++)
#pragma unroll
        for (int c = 0; c < 4; c++) oacc[a][c] = 0.f;

#pragma unroll
    for (int kt = 0; kt < 4; kt++) {
        uint32_t ah[4], al[4];
        ah[0] = pack_hi(sacc[2 * kt][0], sacc[2 * kt][1]);
        ah[1] = pack_hi(sacc[2 * kt][2], sacc[2 * kt][3]);
        ah[2] = pack_hi(sacc[2 * kt + 1][0], sacc[2 * kt + 1][1]);
        ah[3] = pack_hi(sacc[2 * kt + 1][2], sacc[2 * kt + 1][3]);
        al[0] = pack_lo(sacc[2 * kt][0], sacc[2 * kt][1]);
        al[1] = pack_lo(sacc[2 * kt][2], sacc[2 * kt][3]);
        al[2] = pack_lo(sacc[2 * kt + 1][0], sacc[2 * kt + 1][1]);
        al[3] = pack_lo(sacc[2 * kt + 1][2], sacc[2 * kt + 1][3]);
        uint32_t bv[4][2][2];
#pragma unroll
        for (int g = 0; g < 2; g++)
#pragma unroll
            for (int sp = 0; sp < 2; sp++) {
                uint32_t r4[4];
                ldsm4(r4, smb + FVt * 4 +
                    ((((h * 2 + sp) * 32 + g * 16 + b_n_off) * 72 + kt * 16 + b_c_off * 8) << 1));
                bv[g * 2][sp][0] = r4[0]; bv[g * 2][sp][1] = r4[1];
                bv[g * 2 + 1][sp][0] = r4[2]; bv[g * 2 + 1][sp][1] = r4[3];
            }
#pragma unroll
        for (int n = 0; n < 4; n++) {
            mma_bf16(oacc[n], ah, bv[n][0]);
            mma_bf16(oacc[n], ah, bv[n][1]);
            mma_bf16(oacc[n], al, bv[n][0]);
        }
    }

    /* ---- O fragments -> proj-A split-bf16 swizzled (region 0) ---- */
#pragma unroll
    for (int n = 0; n < 4; n++)
#pragma unroll
        for (int rh = 0; rh < 2; rh++) {
            int row = amt * 16 + (l >> 2) + rh * 8;
            int c = h * 32 + n * 8 + cbase;
            float v0 = oacc[n][rh * 2], v1 = oacc[n][rh * 2 + 1];
            int sw = (((c >> 3) ^ (row & 7)) << 3) + (c & 7);
            *(uint32_t*)&u16b[row * 128 + sw]        = pack_hi(v0, v1);
            *(uint32_t*)&u16b[(64 + row) * 128 + sw] = pack_lo(v0, v1);
        }
    __syncthreads();

    /* ======== proj GEMM: D[64x128] = O @ proj_w^T, split-bf16 ======== */
    float pacc[2][2][4];
#pragma unroll
    for (int a = 0; a < 2; a++)
#pragma unroll
        for (int b = 0; b < 2; b++)
#pragma unroll
            for (int c = 0; c < 4; c++) pacc[a][b][c] = 0.f;

#pragma unroll
    for (int kk = 0; kk < 8; kk++) {
        uint32_t af[2][2][4];
#pragma unroll
        for (int mt2 = 0; mt2 < 2; mt2++)
#pragma unroll
            for (int sp = 0; sp < 2; sp++) {
                int r = wm * 32 + mt2 * 16 + a_r_off;
                int ch = kk * 2 + a_c_off;
                uint32_t ad = smb + ((((sp * 64 + r) * 128) + ((ch ^ (r & 7)) << 3)) << 1);
                ldsm4(af[mt2][sp], ad);
            }
        uint32_t bf2[2][2][2];
#pragma unroll
        for (int sp = 0; sp < 2; sp++) {
            int n = wn * 16 + b_n_off;
            int ch = kk * 2 + b_c_off;
            uint32_t ad = smb + FB * 4 + ((((sp * 128 + n) * 128) + ((ch ^ (n & 7)) << 3)) << 1);
            uint32_t r4[4]; ldsm4(r4, ad);
            bf2[0][sp][0] = r4[0]; bf2[0][sp][1] = r4[1];
            bf2[1][sp][0] = r4[2]; bf2[1][sp][1] = r4[3];
        }
#pragma unroll
        for (int mt2 = 0; mt2 < 2; mt2++)
#pragma unroll
            for (int nt = 0; nt < 2; nt++) {
                mma_bf16(pacc[mt2][nt], af[mt2][0], bf2[nt][0]);
                mma_bf16(pacc[mt2][nt], af[mt2][0], bf2[nt][1]);
                mma_bf16(pacc[mt2][nt], af[mt2][1], bf2[nt][0]);
            }
    }
    __syncthreads();

    /* ---- proj epilogue: accum+bias -> bounce -> coalesced store ---- */
    {
        int r0p = wm * 32 + (l >> 2);
#pragma unroll
        for (int mt2 = 0; mt2 < 2; mt2++)
#pragma unroll
            for (int nt = 0; nt < 2; nt++)
#pragma unroll
                for (int rg = 0; rg < 4; rg++) {
                    int row = r0p + mt2 * 16 + ((rg >> 1) << 3);
                    int col = wn * 16 + nt * 8 + (l & 3) * 2 + (rg & 1);
                    if (row < NT)
                        sm[F_BOUNCE + row * BO_LD + col] = pacc[mt2][nt][rg] + sm[F_PB + col];
                }
    }
    __syncthreads();
    for (int idx = t; idx < NT * CD; idx += 512)
        out[base + idx] = sm[F_BOUNCE + (idx >> 7) * BO_LD + (idx & 127)];
}

extern "C" void kernel_launch(void* const* d_in, const int* in_sizes, int n_in,
                              void* d_out, int out_size) {
    const float* x      = (const float*)d_in[0];
    const float* mask   = (const float*)d_in[1];
    const float* qkv_w  = (const float*)d_in[2];
    const float* qkv_b  = (const float*)d_in[3];
    const float* proj_w = (const float*)d_in[4];
    const float* proj_b = (const float*)d_in[5];
    const float* bt     = (const float*)d_in[6];
    float* out = (float*)d_out;

    int B  = in_sizes[0] / (NT * CD);     /* 16384 */
    int nW = in_sizes[1] / (NT * NT);     /* 1024 */

    prep_w<<<96, 512>>>(qkv_w, proj_w);

    cudaFuncSetAttribute(win_attn_mma,
                         cudaFuncAttributeMaxDynamicSharedMemorySize, SMEM_BYTES);
    win_attn_mma<<<B, 512, SMEM_BYTES>>>(x, mask, qkv_b, proj_b, bt, out, nW);
}

// round 9
// speedup vs baseline: 1.1489x; 1.0014x over previous
#include <cuda_runtime.h>
#include <cuda_bf16.h>
#include <cstdint>

#define NT 49
#define CD 128

/* float-index smem offsets */
#define FB      8192      /* QKV B slab (48KB) / proj B both splits (64KB) */
#define FQb     24576     /* Q split-bf16 [4][2][64][40] */
#define FKb     34816     /* K split-bf16 [4][2][64][40] */
#define FVt     45056     /* V^T split-bf16 [4][2][32][72] */
#define F_BT    54272     /* bias table 676 f32 */
#define F_RPI   54948     /* rpi u8 [2401] */
#define F_QB    55549     /* qkv_b 384 */
#define F_PB    55933     /* proj_b 128 */
#define F_BOUNCE 24576    /* out bounce [49][132] (Qb dead) */
#define BO_LD   132
#define SMEM_BYTES (56064*4)

__device__ __align__(16) uint16_t g_qkvw[98304];  /* [slab2][split2][384][64] swizzled bf16 */
__device__ __align__(16) uint16_t g_projw[32768]; /* [split2][128][128] swizzled bf16 */

__device__ __forceinline__ uint32_t smem_u32(const void* p) {
    uint32_t a;
    asm("{ .reg .u64 t; cvta.to.shared.u64 t, %1; cvt.u32.u64 %0, t; }" : "=r"(a) : "l"(p));
    return a;
}
__device__ __forceinline__ void ldsm4(uint32_t* r, uint32_t a) {
    asm volatile("ldmatrix.sync.aligned.m8n8.x4.shared.b16 {%0,%1,%2,%3}, [%4];"
        : "=r"(r[0]), "=r"(r[1]), "=r"(r[2]), "=r"(r[3]) : "r"(a));
}
__device__ __forceinline__ void mma_bf16(float* d, const uint32_t* a, const uint32_t* b) {
    asm volatile("mma.sync.aligned.m16n8k16.row.col.f32.bf16.bf16.f32 "
        "{%0,%1,%2,%3}, {%4,%5,%6,%7}, {%8,%9}, {%0,%1,%2,%3};"
        : "+f"(d[0]), "+f"(d[1]), "+f"(d[2]), "+f"(d[3])
        : "r"(a[0]), "r"(a[1]), "r"(a[2]), "r"(a[3]), "r"(b[0]), "r"(b[1]));
}
__device__ __forceinline__ uint32_t pack_hi(float a, float b) {
    __nv_bfloat16 h0 = __float2bfloat16_rn(a), h1 = __float2bfloat16_rn(b);
    return (uint32_t)__bfloat16_as_ushort(h0) | ((uint32_t)__bfloat16_as_ushort(h1) << 16);
}
__device__ __forceinline__ uint32_t pack_lo(float a, float b) {
    __nv_bfloat16 h0 = __float2bfloat16_rn(a), h1 = __float2bfloat16_rn(b);
    float l0 = a - __bfloat162float(h0), l1 = b - __bfloat162float(h1);
    return (uint32_t)__bfloat16_as_ushort(__float2bfloat16_rn(l0)) |
           ((uint32_t)__bfloat16_as_ushort(__float2bfloat16_rn(l1)) << 16);
}

/* ---- prologue: split weights into bf16 hi/lo swizzled smem-images ---- */
__global__ void prep_w(const float* __restrict__ qkv_w, const float* __restrict__ proj_w) {
    int i = blockIdx.x * blockDim.x + threadIdx.x;
    if (i < 384 * 128) {
        int n = i >> 7, k = i & 127;
        float f = qkv_w[i];
        __nv_bfloat16 h = __float2bfloat16_rn(f);
        __nv_bfloat16 l = __float2bfloat16_rn(f - __bfloat162float(h));
        int s = k >> 6, ko = k & 63;
        int sw = (((ko >> 3) ^ (n & 7)) << 3) + (k & 7);
        g_qkvw[((s * 2 + 0) * 384 + n) * 64 + sw] = __bfloat16_as_ushort(h);
        g_qkvw[((s * 2 + 1) * 384 + n) * 64 + sw] = __bfloat16_as_ushort(l);
    }
    if (i < 128 * 128) {
        int n = i >> 7, k = i & 127;
        float f = proj_w[i];
        __nv_bfloat16 h = __float2bfloat16_rn(f);
        __nv_bfloat16 l = __float2bfloat16_rn(f - __bfloat162float(h));
        int sw = (((k >> 3) ^ (n & 7)) << 3) + (k & 7);
        g_projw[(0 * 128 + n) * 128 + sw] = __bfloat16_as_ushort(h);
        g_projw[(1 * 128 + n) * 128 + sw] = __bfloat16_as_ushort(l);
    }
}

/* ---- main fused kernel ---- */
__global__ __launch_bounds__(512, 1)
void win_attn_mma(const float* __restrict__ x,
                  const float* __restrict__ mask,
                  const float* __restrict__ qkv_b,
                  const float* __restrict__ proj_b,
                  const float* __restrict__ bt,
                  float* __restrict__ out,
                  int nW)
{
    extern __shared__ float sm[];
    uint16_t* u16b = (uint16_t*)sm;
    const int t = threadIdx.x;
    const int w = blockIdx.x;
    const long base = (long)w * (NT * CD);
    const int tn = t & 31, tm = t >> 5;
    const uint32_t smb = smem_u32(sm);

    /* ---- stage x -> A hi/lo (swizzled bf16); pads; tables; biases ---- */
    for (int idx = t; idx < NT * CD; idx += 512) {
        int r = idx >> 7, k = idx & 127;
        float f = x[base + idx];
        __nv_bfloat16 h = __float2bfloat16_rn(f);
        __nv_bfloat16 l = __float2bfloat16_rn(f - __bfloat162float(h));
        int sw = ((k >> 3) ^ (r & 7)) * 8 + (k & 7);
        u16b[r * 128 + sw]        = __bfloat16_as_ushort(h);
        u16b[(64 + r) * 128 + sw] = __bfloat16_as_ushort(l);
    }
    for (int idx = t; idx < 15 * CD; idx += 512) {
        int r = 49 + (idx >> 7), k = idx & 127;
        int sw = ((k >> 3) ^ (r & 7)) * 8 + (k & 7);
        u16b[r * 128 + sw] = 0;
        u16b[(64 + r) * 128 + sw] = 0;
    }
    if (t < 384) sm[F_QB + t] = qkv_b[t];
    if (t < 128) sm[F_PB + t] = proj_b[t];
    for (int idx = t; idx < 676; idx += 512) sm[F_BT + idx] = bt[idx];
    {   /* rpi table u8[49][49] */
        uint8_t* rpw = (uint8_t*)(sm + F_RPI);
        for (int idx = t; idx < NT * NT; idx += 512) {
            int i = idx / NT, j = idx - i * NT;
            int yi = i / 7, xi = i - yi * 7;
            int yj = j / 7, xj = j - yj * 7;
            rpw[idx] = (uint8_t)((yi - yj + 6) * 13 + (xi - xj + 6));
        }
    }
    __syncthreads();

    const int l = tn;
    const int wm = tm & 1, wn = tm >> 1;
    const int a_r_off = l & 15;
    const int a_c_off = l >> 4;
    const int b_n_off = (l & 7) + (l >> 4) * 8;
    const int b_c_off = (l >> 3) & 1;

    /* ======== QKV GEMM: D[64x384] = A[64x128] @ W^T, split-bf16 ======== */
    float dacc[2][6][4];
#pragma unroll
    for (int a = 0; a < 2; a++)
#pragma unroll
        for (int b = 0; b < 6; b++)
#pragma unroll
            for (int c = 0; c < 4; c++) dacc[a][b][c] = 0.f;

    for (int s = 0; s < 2; s++)
        for (int bsp = 0; bsp < 2; bsp++) {
            {   /* stage one split of B k-slab: [384][64] bf16 = 3072 float4 */
                const float4* src = ((const float4*)g_qkvw) + (s * 2 + bsp) * 3072;
                float4* dst = (float4*)(sm + FB);
                for (int i = t; i < 3072; i += 512) dst[i] = src[i];
            }
            __syncthreads();
#pragma unroll
            for (int kk = 0; kk < 4; kk++) {
                uint32_t afh[2][4], afl[2][4];
#pragma unroll
                for (int mt = 0; mt < 2; mt++) {
                    int r = wm * 32 + mt * 16 + a_r_off;
                    int ch = s * 8 + kk * 2 + a_c_off;
                    uint32_t ad = smb + (((r * 128) + ((ch ^ (r & 7)) << 3)) << 1);
                    ldsm4(afh[mt], ad);
                    if (bsp == 0) ldsm4(afl[mt], ad + (64 * 128 * 2));
                }
                uint32_t bf[6][2];
#pragma unroll
                for (int np = 0; np < 3; np++) {
                    int n = wn * 48 + np * 16 + b_n_off;
                    int ch = kk * 2 + b_c_off;
                    uint32_t ad = smb + FB * 4 + (((n * 64) + ((ch ^ (n & 7)) << 3)) << 1);
                    uint32_t r4[4]; ldsm4(r4, ad);
                    bf[np * 2][0] = r4[0]; bf[np * 2][1] = r4[1];
                    bf[np * 2 + 1][0] = r4[2]; bf[np * 2 + 1][1] = r4[3];
                }
#pragma unroll
                for (int mt = 0; mt < 2; mt++)
#pragma unroll
                    for (int nt = 0; nt < 6; nt++) {
                        mma_bf16(dacc[mt][nt], afh[mt], bf[nt]);
                        if (bsp == 0) mma_bf16(dacc[mt][nt], afl[mt], bf[nt]);
                    }
            }
            __syncthreads();
        }

    /* ---- QKV epilogue: fragments -> Qb (x scale) / Kb / Vt, split-bf16 ---- */
    {
        const float scale = 0.1767766952966369f;
        int r0 = wm * 32 + (l >> 2);
#pragma unroll
        for (int mt = 0; mt < 2; mt++)
#pragma unroll
            for (int nt = 0; nt < 6; nt++)
#pragma unroll
                for (int rh = 0; rh < 2; rh++) {
                    int row = r0 + mt * 16 + rh * 8;
                    if (row >= NT) continue;
                    int c = wn * 48 + nt * 8 + (l & 3) * 2;
                    float v0 = dacc[mt][nt][rh * 2]     + sm[F_QB + c];
                    float v1 = dacc[mt][nt][rh * 2 + 1] + sm[F_QB + c + 1];
                    if (c < 128) {
                        v0 *= scale; v1 *= scale;
                        int h = c >> 5, dh = c & 31;
                        int i0 = ((h * 2 + 0) * 64 + row) * 40 + dh;
                        int i1 = ((h * 2 + 1) * 64 + row) * 40 + dh;
                        *(uint32_t*)&u16b[FQb * 2 + i0] = pack_hi(v0, v1);
                        *(uint32_t*)&u16b[FQb * 2 + i1] = pack_lo(v0, v1);
                    } else if (c < 256) {
                        int h = (c - 128) >> 5, dh = (c - 128) & 31;
                        int i0 = ((h * 2 + 0) * 64 + row) * 40 + dh;
                        int i1 = ((h * 2 + 1) * 64 + row) * 40 + dh;
                        *(uint32_t*)&u16b[FKb * 2 + i0] = pack_hi(v0, v1);
                        *(uint32_t*)&u16b[FKb * 2 + i1] = pack_lo(v0, v1);
                    } else {
                        int h = (c - 256) >> 5, dh = (c - 256) & 31;
                        __nv_bfloat16 h0 = __float2bfloat16_rn(v0);
                        __nv_bfloat16 h1 = __float2bfloat16_rn(v1);
                        __nv_bfloat16 l0 = __float2bfloat16_rn(v0 - __bfloat162float(h0));
                        __nv_bfloat16 l1 = __float2bfloat16_rn(v1 - __bfloat162float(h1));
                        int bh = FVt * 2 + ((h * 2 + 0) * 32 + dh) * 72 + row;
                        int bl = FVt * 2 + ((h * 2 + 1) * 32 + dh) * 72 + row;
                        u16b[bh]      = __bfloat16_as_ushort(h0);
                        u16b[bh + 72] = __bfloat16_as_ushort(h1);
                        u16b[bl]      = __bfloat16_as_ushort(l0);
                        u16b[bl + 72] = __bfloat16_as_ushort(l1);
                    }
                }
    }
    /* zero Vt key-pad cols 49..63 (0*garbage != NaN safety) */
    for (int i = t; i < 8 * 32 * 15; i += 512) {
        int hs = i / (32 * 15), rem = i - hs * (32 * 15);
        int dh = rem / 15, jj = rem - dh * 15;
        u16b[FVt * 2 + (hs * 32 + dh) * 72 + 49 + jj] = 0;
    }
    /* stage proj B now (both splits, 4096 float4) — latency hides behind attention */
    {
        const float4* src = (const float4*)g_projw;
        float4* dst = (float4*)(sm + FB);
        for (int i = t; i < 4096; i += 512) dst[i] = src[i];
    }
    __syncthreads();

    /* ======== attention, fully register-resident: 16 warps = 4 heads x 4 m-tiles ======== */
    const float* mrow = mask + (long)(w % nW) * (NT * NT);
    const uint8_t* rp = (const uint8_t*)(sm + F_RPI);
    const int h = tm >> 2, amt = tm & 3;
    const int cbase = (l & 3) * 2;
    const int r0 = amt * 16 + (l >> 2);
    const int r1 = r0 + 8;

    /* ---- S = (Q*scale) K^T : m16 x n64 per warp ---- */
    float sacc[8][4];
#pragma unroll
    for (int a = 0; a < 8; a++)
#pragma unroll
        for (int c = 0; c < 4; c++) sacc[a][c] = 0.f;

#pragma unroll
    for (int kk = 0; kk < 2; kk++) {
        uint32_t aq[2][4];
#pragma unroll
        for (int sp = 0; sp < 2; sp++)
            ldsm4(aq[sp], smb + FQb * 4 +
                ((((h * 2 + sp) * 64 + amt * 16 + a_r_off) * 40 + (kk * 2 + a_c_off) * 8) << 1));
        uint32_t bk[8][2][2];
#pragma unroll
        for (int g = 0; g < 4; g++)
#pragma unroll
            for (int sp = 0; sp < 2; sp++) {
                uint32_t r4[4];
                ldsm4(r4, smb + FKb * 4 +
                    ((((h * 2 + sp) * 64 + g * 16 + b_n_off) * 40 + (kk * 2 + b_c_off) * 8) << 1));
                bk[g * 2][sp][0] = r4[0]; bk[g * 2][sp][1] = r4[1];
                bk[g * 2 + 1][sp][0] = r4[2]; bk[g * 2 + 1][sp][1] = r4[3];
            }
#pragma unroll
        for (int nt = 0; nt < 8; nt++) {
            mma_bf16(sacc[nt], aq[0], bk[nt][0]);
            mma_bf16(sacc[nt], aq[0], bk[nt][1]);
            mma_bf16(sacc[nt], aq[1], bk[nt][0]);
        }
    }

    /* ---- softmax in registers (+bias+mask); rows reduce over 4 lanes ---- */
    {
        int r0c = (r0 < NT) ? r0 : (NT - 1);
        int r1c = (r1 < NT) ? r1 : (NT - 1);
        float m0 = -1e30f, m1 = -1e30f;
#pragma unroll
        for (int nt = 0; nt < 8; nt++)
#pragma unroll
            for (int j = 0; j < 2; j++) {
                int c = nt * 8 + cbase + j;
                if (c < NT) {
                    float bi0 = sm[F_BT + rp[r0c * NT + c] * 4 + h];
                    float bi1 = sm[F_BT + rp[r1c * NT + c] * 4 + h];
                    float mk0 = (r0 < NT) ? mrow[r0 * NT + c] : 0.f;
                    float mk1 = (r1 < NT) ? mrow[r1 * NT + c] : 0.f;
                    sacc[nt][j]     += bi0 + mk0;
                    sacc[nt][2 + j] += bi1 + mk1;
                } else {
                    sacc[nt][j] = -1e30f;
                    sacc[nt][2 + j] = -1e30f;
                }
                m0 = fmaxf(m0, sacc[nt][j]);
                m1 = fmaxf(m1, sacc[nt][2 + j]);
            }
        m0 = fmaxf(m0, __shfl_xor_sync(0xffffffffu, m0, 1));
        m0 = fmaxf(m0, __shfl_xor_sync(0xffffffffu, m0, 2));
        m1 = fmaxf(m1, __shfl_xor_sync(0xffffffffu, m1, 1));
        m1 = fmaxf(m1, __shfl_xor_sync(0xffffffffu, m1, 2));
        float s0 = 0.f, s1 = 0.f;
#pragma unroll
        for (int nt = 0; nt < 8; nt++)
#pragma unroll
            for (int j = 0; j < 2; j++) {
                float e0 = __expf(sacc[nt][j] - m0);
                float e1 = __expf(sacc[nt][2 + j] - m1);
                sacc[nt][j] = e0; sacc[nt][2 + j] = e1;
                s0 += e0; s1 += e1;
            }
        s0 += __shfl_xor_sync(0xffffffffu, s0, 1);
        s0 += __shfl_xor_sync(0xffffffffu, s0, 2);
        s1 += __shfl_xor_sync(0xffffffffu, s1, 1);
        s1 += __shfl_xor_sync(0xffffffffu, s1, 2);
        float i0 = 1.f / s0, i1 = 1.f / s1;
#pragma unroll
        for (int nt = 0; nt < 8; nt++)
#pragma unroll
            for (int j = 0; j < 2; j++) { sacc[nt][j] *= i0; sacc[nt][2 + j] *= i1; }
    }

    /* ---- O = P V : P fragments straight from registers (D-layout == A-layout) ---- */
    float oacc[4][4];
#pragma unroll
    for (int a = 0; a < 4; a++)
#pragma unroll
        for (int c = 0; c < 4; c++) oacc[a][c] = 0.f;

#pragma unroll
    for (int kt = 0; kt < 4; kt++) {
        uint32_t ah[4], al[4];
        ah[0] = pack_hi(sacc[2 * kt][0], sacc[2 * kt][1]);
        ah[1] = pack_hi(sacc[2 * kt][2], sacc[2 * kt][3]);
        ah[2] = pack_hi(sacc[2 * kt + 1][0], sacc[2 * kt + 1][1]);
        ah[3] = pack_hi(sacc[2 * kt + 1][2], sacc[2 * kt + 1][3]);
        al[0] = pack_lo(sacc[2 * kt][0], sacc[2 * kt][1]);
        al[1] = pack_lo(sacc[2 * kt][2], sacc[2 * kt][3]);
        al[2] = pack_lo(sacc[2 * kt + 1][0], sacc[2 * kt + 1][1]);
        al[3] = pack_lo(sacc[2 * kt + 1][2], sacc[2 * kt + 1][3]);
        uint32_t bv[4][2][2];
#pragma unroll
        for (int g = 0; g < 2; g++)
#pragma unroll
            for (int sp = 0; sp < 2; sp++) {
                uint32_t r4[4];
                ldsm4(r4, smb + FVt * 4 +
                    ((((h * 2 + sp) * 32 + g * 16 + b_n_off) * 72 + kt * 16 + b_c_off * 8) << 1));
                bv[g * 2][sp][0] = r4[0]; bv[g * 2][sp][1] = r4[1];
                bv[g * 2 + 1][sp][0] = r4[2]; bv[g * 2 + 1][sp][1] = r4[3];
            }
#pragma unroll
        for (int n = 0; n < 4; n++) {
            mma_bf16(oacc[n], ah, bv[n][0]);
            mma_bf16(oacc[n], ah, bv[n][1]);
            mma_bf16(oacc[n], al, bv[n][0]);
        }
    }

    /* ---- O fragments -> proj-A split-bf16 swizzled (region 0) ---- */
#pragma unroll
    for (int n = 0; n < 4; n++)
#pragma unroll
        for (int rh = 0; rh < 2; rh++) {
            int row = amt * 16 + (l >> 2) + rh * 8;
            int c = h * 32 + n * 8 + cbase;
            float v0 = oacc[n][rh * 2], v1 = oacc[n][rh * 2 + 1];
            int sw = (((c >> 3) ^ (row & 7)) << 3) + (c & 7);
            *(uint32_t*)&u16b[row * 128 + sw]        = pack_hi(v0, v1);
            *(uint32_t*)&u16b[(64 + row) * 128 + sw] = pack_lo(v0, v1);
        }
    __syncthreads();

    /* ======== proj GEMM: D[64x128] = O @ proj_w^T, split-bf16 ======== */
    float pacc[2][2][4];
#pragma unroll
    for (int a = 0; a < 2; a++)
#pragma unroll
        for (int b = 0; b < 2; b++)
#pragma unroll
            for (int c = 0; c < 4; c++) pacc[a][b][c] = 0.f;

#pragma unroll
    for (int kk = 0; kk < 8; kk++) {
        uint32_t af[2][2][4];
#pragma unroll
        for (int mt2 = 0; mt2 < 2; mt2++)
#pragma unroll
            for (int sp = 0; sp < 2; sp++) {
                int r = wm * 32 + mt2 * 16 + a_r_off;
                int ch = kk * 2 + a_c_off;
                uint32_t ad = smb + ((((sp * 64 + r) * 128) + ((ch ^ (r & 7)) << 3)) << 1);
                ldsm4(af[mt2][sp], ad);
            }
        uint32_t bf2[2][2][2];
#pragma unroll
        for (int sp = 0; sp < 2; sp++) {
            int n = wn * 16 + b_n_off;
            int ch = kk * 2 + b_c_off;
            uint32_t ad = smb + FB * 4 + ((((sp * 128 + n) * 128) + ((ch ^ (n & 7)) << 3)) << 1);
            uint32_t r4[4]; ldsm4(r4, ad);
            bf2[0][sp][0] = r4[0]; bf2[0][sp][1] = r4[1];
            bf2[1][sp][0] = r4[2]; bf2[1][sp][1] = r4[3];
        }
#pragma unroll
        for (int mt2 = 0; mt2 < 2; mt2++)
#pragma unroll
            for (int nt = 0; nt < 2; nt++) {
                mma_bf16(pacc[mt2][nt], af[mt2][0], bf2[nt][0]);
                mma_bf16(pacc[mt2][nt], af[mt2][0], bf2[nt][1]);
                mma_bf16(pacc[mt2][nt], af[mt2][1], bf2[nt][0]);
            }
    }
    __syncthreads();

    /* ---- proj epilogue: accum+bias -> bounce -> coalesced store ---- */
    {
        int r0p = wm * 32 + (l >> 2);
#pragma unroll
        for (int mt2 = 0; mt2 < 2; mt2++)
#pragma unroll
            for (int nt = 0; nt < 2; nt++)
#pragma unroll
                for (int rg = 0; rg < 4; rg++) {
                    int row = r0p + mt2 * 16 + ((rg >> 1) << 3);
                    int col = wn * 16 + nt * 8 + (l & 3) * 2 + (rg & 1);
                    if (row < NT)
                        sm[F_BOUNCE + row * BO_LD + col] = pacc[mt2][nt][rg] + sm[F_PB + col];
                }
    }
    __syncthreads();
    for (int idx = t; idx < NT * CD; idx += 512)
        out[base + idx] = sm[F_BOUNCE + (idx >> 7) * BO_LD + (idx & 127)];
}

extern "C" void kernel_launch(void* const* d_in, const int* in_sizes, int n_in,
                              void* d_out, int out_size) {
    const float* x      = (const float*)d_in[0];
    const float* mask   = (const float*)d_in[1];
    const float* qkv_w  = (const float*)d_in[2];
    const float* qkv_b  = (const float*)d_in[3];
    const float* proj_w = (const float*)d_in[4];
    const float* proj_b = (const float*)d_in[5];
    const float* bt     = (const float*)d_in[6];
    float* out = (float*)d_out;

    int B  = in_sizes[0] / (NT * CD);     /* 16384 */
    int nW = in_sizes[1] / (NT * NT);     /* 1024 */

    prep_w<<<96, 512>>>(qkv_w, proj_w);

    cudaFuncSetAttribute(win_attn_mma,
                         cudaFuncAttributeMaxDynamicSharedMemorySize, SMEM_BYTES);
    win_attn_mma<<<B, 512, SMEM_BYTES>>>(x, mask, qkv_b, proj_b, bt, out, nW);
}